// round 15
// baseline (speedup 1.0000x reference)
#include <cuda_runtime.h>
#include <cuda_fp16.h>
#include <math.h>
#include <float.h>
#include <stdint.h>

#define B_    1024
#define L_    128
#define DIN   130
#define H_    768
#define FEAT_ 49
#define PROJ_ 40
#define NG    3072          // 4*H
#define NATT  384           // 3*L
#define NCHK  37            // K chunks of 32: v chunks 0..12, h chunks 13..36
#define KTOT  1184
#define HOFF  416           // h starts at k=416 (chunk 13)
#define NSTG  4

typedef __half f16;

// ---------------- device scratch (chunked, swizzled layouts) ----------------
__device__ f16 g_Ahi0[NCHK*B_*32], g_Alo0[NCHK*B_*32];
__device__ f16 g_Ahi1[NCHK*B_*32], g_Alo1[NCHK*B_*32];
__device__ f16 g_Whi[NCHK*NG*32];                       // gates W^T chunked [c][n_perm][32]
__device__ f16 g_Lhi[24*NATT*32];                       // logits W^T chunked [c][n][32]
__device__ f16 g_Xh[B_*L_*DIN];                         // X in fp16
__device__ float g_bsum[NG];
__device__ float g_c[B_*H_], g_hmax[B_*H_];
__device__ float g_logits[B_*NATT];

// ---------------- helpers ----------------
__device__ __forceinline__ uint32_t smem_u32(const void* p) {
    return (uint32_t)__cvta_generic_to_shared(p);
}
__device__ __forceinline__ int swz(int row, int kk) {
    int seg = ((kk >> 3) ^ (row + (row >> 2))) & 3;
    return row * 32 + seg * 8 + (kk & 7);
}
__device__ __forceinline__ void bulk_cp(uint32_t dst, const void* src, uint32_t bytes,
                                        uint32_t mbar) {
    asm volatile("cp.async.bulk.shared::cluster.global.mbarrier::complete_tx::bytes "
                 "[%0], [%1], %2, [%3];"
                 :: "r"(dst), "l"(__cvta_generic_to_global(src)), "r"(bytes), "r"(mbar)
                 : "memory");
}
__device__ __forceinline__ void mbar_init(uint32_t a, uint32_t cnt) {
    asm volatile("mbarrier.init.shared.b64 [%0], %1;" :: "r"(a), "r"(cnt) : "memory");
}
__device__ __forceinline__ void mbar_expect(uint32_t a, uint32_t tx) {
    asm volatile("mbarrier.arrive.expect_tx.shared.b64 _, [%0], %1;"
                 :: "r"(a), "r"(tx) : "memory");
}
__device__ __forceinline__ void mbar_wait(uint32_t a, uint32_t ph) {
    asm volatile(
        "{\n\t.reg .pred P;\n"
        "WL%=:\n\t"
        "mbarrier.try_wait.parity.acquire.cta.shared::cta.b64 P, [%0], %1, 0x989680;\n\t"
        "@P bra WD%=;\n\t"
        "bra WL%=;\n"
        "WD%=:\n\t}"
        :: "r"(a), "r"(ph) : "memory");
}

#define LDSM4(r, a) \
    asm volatile("ldmatrix.sync.aligned.m8n8.x4.shared.b16 {%0,%1,%2,%3}, [%4];" \
        : "=r"((r)[0]), "=r"((r)[1]), "=r"((r)[2]), "=r"((r)[3]) : "r"(a))

__device__ __forceinline__ void mma16816(float* d, const uint32_t* a, const uint32_t* b) {
    asm volatile("mma.sync.aligned.m16n8k16.row.col.f32.f16.f16.f32 "
        "{%0,%1,%2,%3}, {%4,%5,%6,%7}, {%8,%9}, {%0,%1,%2,%3};"
        : "+f"(d[0]), "+f"(d[1]), "+f"(d[2]), "+f"(d[3])
        : "r"(a[0]), "r"(a[1]), "r"(a[2]), "r"(a[3]), "r"(b[0]), "r"(b[1]));
}

__device__ __forceinline__ float sigmf(float x) { return 1.0f / (1.0f + __expf(-x)); }

// ---------------- init ----------------
// permuted col n = 16q + 8h + 2a + e  <->  gate (2h+e) of hidden j = 4q + a
__global__ void k_init(const float* __restrict__ X,
                       const float* __restrict__ W_att, const float* __restrict__ W_ih,
                       const float* __restrict__ W_hh, const float* __restrict__ b_ih,
                       const float* __restrict__ b_hh) {
    long g = (long)blockIdx.x * blockDim.x + threadIdx.x;
    long stride = (long)gridDim.x * blockDim.x;
    for (long i = g; i < (long)NG * KTOT; i += stride) {
        int n = (int)(i / KTOT), k = (int)(i % KTOT);
        int q = n >> 4, r = n & 15;
        int gate = ((r >> 3) << 1) | (r & 1);
        int j = (q << 2) + ((r & 7) >> 1);
        int srow = gate * H_ + j;
        float w = 0.0f;
        if (k < 390)                         w = W_ih[(size_t)srow * 390 + k];
        else if (k >= HOFF && k < HOFF + H_) w = W_hh[(size_t)srow * H_ + (k - HOFF)];
        g_Whi[(size_t)(k >> 5) * (NG * 32) + swz(n, k & 31)] = __float2half_rn(w);
    }
    for (long i = g; i < (long)NATT * H_; i += stride) {
        int n = (int)(i / H_), k = (int)(i % H_);
        int ks = n >> 7, l = n & 127;
        float w = W_att[(size_t)ks * (H_ * L_) + (size_t)k * L_ + l];
        g_Lhi[(size_t)(k >> 5) * (NATT * 32) + swz(n, k & 31)] = __float2half_rn(w);
    }
    for (long i = g; i < (long)B_ * L_ * DIN; i += stride)
        g_Xh[i] = __float2half_rn(X[i]);
    for (long i = g; i < NG; i += stride) {
        int n = (int)i;
        int q = n >> 4, r = n & 15;
        int gate = ((r >> 3) << 1) | (r & 1);
        int j = (q << 2) + ((r & 7) >> 1);
        g_bsum[i] = b_ih[gate * H_ + j] + b_hh[gate * H_ + j];
    }
    f16 z = __float2half_rn(0.0f);
    for (long i = g; i < (long)NCHK * B_ * 32; i += stride) {
        g_Ahi0[i] = z; g_Alo0[i] = z; g_Ahi1[i] = z; g_Alo1[i] = z;
    }
    for (long i = g; i < (long)B_ * H_; i += stride) { g_c[i] = 0.0f; g_hmax[i] = -FLT_MAX; }
}

// ---------------- bulk-fed mma.sync GEMM, fp16 A-hi/lo x B (2 products) ----------------
// Warp tile WM x WN. NSTG-stage mbarrier ring fed by cp.async.bulk.
template <int BM, int BN, int WM, int WN, bool GATES, int BROWS, int NCH, int CA0>
__global__ void __launch_bounds__((BM / WM) * (BN / WN) * 32, 1)
k_mma(const f16* __restrict__ gAhi, const f16* __restrict__ gAlo,
      f16* __restrict__ wAhi, f16* __restrict__ wAlo,
      const f16* __restrict__ gBhi, const float* __restrict__ bias) {
    constexpr int NWX = BN / WN, NWY = BM / WM;
    constexpr int MT = WM / 16;
    constexpr int NTHR = NWX * NWY * 32;
    constexpr int NB16 = WN / 16;
    constexpr uint32_t A_BYTES = (uint32_t)BM * 64u;
    constexpr uint32_t B_BYTES = (uint32_t)BN * 64u;
    constexpr uint32_t STAGE_B = 2u * A_BYTES + B_BYTES;
    constexpr uint32_t TXB = STAGE_B;

    extern __shared__ __align__(128) char dyn[];
    __shared__ __align__(8) uint64_t s_mbar[NSTG];
    __shared__ float s_bias[BN];

    const int tid = threadIdx.x, w = tid >> 5, lane = tid & 31;
    const int wx = w % NWX, wy = w / NWX;
    const int m0 = blockIdx.y * BM, n0 = blockIdx.x * BN;
    const uint32_t smb = smem_u32(dyn);
    const uint32_t mb0 = smem_u32(&s_mbar[0]);

    if (tid == 0) {
#pragma unroll
        for (int i = 0; i < NSTG; i++) mbar_init(mb0 + 8u * i, 1);
    }
    for (int i = tid; i < BN; i += NTHR) s_bias[i] = bias[n0 + i];
    __syncthreads();

    auto issue = [&](int k) {
        uint32_t buf = smb + (uint32_t)(k % NSTG) * STAGE_B;
        uint32_t mb = mb0 + 8u * (k % NSTG);
        mbar_expect(mb, TXB);
        const char* srcAh = (const char*)gAhi + ((size_t)(CA0 + k) * B_ + m0) * 64;
        const char* srcAl = (const char*)gAlo + ((size_t)(CA0 + k) * B_ + m0) * 64;
        const char* srcBh = (const char*)gBhi + ((size_t)k * BROWS + n0) * 64;
        bulk_cp(buf,               srcAh, A_BYTES, mb);
        bulk_cp(buf + A_BYTES,     srcAl, A_BYTES, mb);
        bulk_cp(buf + 2 * A_BYTES, srcBh, B_BYTES, mb);
    };
    if (tid == 0) { issue(0); issue(1); issue(2); }

    float acc[MT][WN / 8][4];
#pragma unroll
    for (int i = 0; i < MT; i++)
#pragma unroll
        for (int j = 0; j < WN / 8; j++)
#pragma unroll
            for (int k = 0; k < 4; k++) acc[i][j][k] = 0.0f;

    for (int s = 0; s < NCH; s++) {
        if (tid == 0 && s + 3 < NCH) issue(s + 3);
        mbar_wait(mb0 + 8u * (s % NSTG), (uint32_t)((s / NSTG) & 1));

        const uint32_t st  = smb + (uint32_t)(s % NSTG) * STAGE_B;
        const uint32_t stB = st + 2 * A_BYTES;
#pragma unroll
        for (int ks = 0; ks < 2; ks++) {
            uint32_t ah[MT][4], al[MT][4];
#pragma unroll
            for (int mt = 0; mt < MT; mt++) {
                int row = wy * WM + mt * 16 + (lane & 15);
                int seg = (ks * 2 + (lane >> 4)) ^ ((row + (row >> 2)) & 3);
                uint32_t addr = st + (uint32_t)(row * 64 + (seg & 3) * 16);
                LDSM4(ah[mt], addr);
                LDSM4(al[mt], addr + A_BYTES);
            }
#pragma unroll
            for (int nb = 0; nb < NB16; nb++) {
                uint32_t bh[4];
                {
                    int gg = lane >> 3;
                    int row = wx * WN + nb * 16 + ((gg >> 1) << 3) + (lane & 7);
                    int seg = (ks * 2 + (gg & 1)) ^ ((row + (row >> 2)) & 3);
                    uint32_t addr = stB + (uint32_t)(row * 64 + (seg & 3) * 16);
                    LDSM4(bh, addr);
                }
#pragma unroll
                for (int mt = 0; mt < MT; mt++)
#pragma unroll
                    for (int j2 = 0; j2 < 2; j2++) {
                        float* a = acc[mt][nb * 2 + j2];
                        mma16816(a, ah[mt], &bh[j2 * 2]);
                        mma16816(a, al[mt], &bh[j2 * 2]);
                    }
            }
        }
        __syncthreads();
    }

    const int a_ = lane & 3, rl = lane >> 2;
    if constexpr (GATES) {
        // stage h (hi/lo) in smem, then coalesced uint4 writes
        constexpr int JW = BN / 4;                    // 48 j per CTA
        f16* sh_hi = (f16*)dyn;                       // [BM][JW]
        f16* sh_lo = (f16*)dyn + BM * JW;
        const int j0 = n0 >> 2;
#pragma unroll
        for (int mt = 0; mt < MT; mt++)
#pragma unroll
            for (int p = 0; p < WN / 16; p++) {
                const int colb = wx * WN + p * 16;
                const float bi = s_bias[colb + 2 * a_];
                const float bf = s_bias[colb + 2 * a_ + 1];
                const float bg = s_bias[colb + 8 + 2 * a_];
                const float bo = s_bias[colb + 8 + 2 * a_ + 1];
                const int jl = (colb >> 2) + a_;
                const int j = j0 + jl;
#pragma unroll
                for (int rh = 0; rh < 2; rh++) {
                    float iv = acc[mt][2 * p][2 * rh]     + bi;
                    float fv = acc[mt][2 * p][2 * rh + 1] + bf;
                    float gv = acc[mt][2 * p + 1][2 * rh]     + bg;
                    float ov = acc[mt][2 * p + 1][2 * rh + 1] + bo;
                    int row = wy * WM + mt * 16 + rh * 8 + rl;
                    int b = m0 + row;
                    size_t cidx = (size_t)b * H_ + j;
                    float c = sigmf(fv) * g_c[cidx] + sigmf(iv) * tanhf(gv);
                    float h = sigmf(ov) * tanhf(c);
                    g_c[cidx] = c;
                    g_hmax[cidx] = fmaxf(g_hmax[cidx], h);
                    f16 hh = __float2half_rn(h);
                    sh_hi[row * JW + jl] = hh;
                    sh_lo[row * JW + jl] = __float2half_rn(h - __half2float(hh));
                }
            }
        __syncthreads();
        for (int i = tid; i < BM * (JW / 8); i += NTHR) {
            int row = i / (JW / 8), s8 = i % (JW / 8);
            int j = j0 + s8 * 8;
            int chunk = 13 + (j >> 5);
            int kk = j & 31;
            int b = m0 + row;
            int seg = ((kk >> 3) ^ (b + (b >> 2))) & 3;
            size_t dst = (size_t)chunk * (B_ * 32) + (size_t)b * 32 + seg * 8;
            *(uint4*)(wAhi + dst) = *(const uint4*)(sh_hi + row * JW + s8 * 8);
            *(uint4*)(wAlo + dst) = *(const uint4*)(sh_lo + row * JW + s8 * 8);
        }
    } else {
#pragma unroll
        for (int mt = 0; mt < MT; mt++)
#pragma unroll
            for (int nt = 0; nt < WN / 8; nt++) {
                const int lc = wx * WN + nt * 8 + 2 * a_;
#pragma unroll
                for (int rh = 0; rh < 2; rh++) {
                    int row = m0 + wy * WM + mt * 16 + rh * 8 + rl;
                    float2 v;
                    v.x = acc[mt][nt][2 * rh]     + s_bias[lc];
                    v.y = acc[mt][nt][2 * rh + 1] + s_bias[lc + 1];
                    *(float2*)&g_logits[(size_t)row * NATT + n0 + lc] = v;
                }
            }
    }
}

// ---------------- fused softmax + attention pooling (fp16 X, writes v hi/lo) ----------
__global__ void k_attn(f16* __restrict__ wHi, f16* __restrict__ wLo) {
    __shared__ float alp[NATT];
    __shared__ float xs[16 * DIN];
    __shared__ float red[16];
    const int b = blockIdx.x;
    const int tid = threadIdx.x;
    for (int i = tid; i < NATT; i += 416) alp[i] = g_logits[b * NATT + i];
    __syncthreads();

    const int wid = tid >> 5, lane = tid & 31;
    float xv = (tid < NATT) ? alp[tid] : -FLT_MAX;
    float m = xv;
#pragma unroll
    for (int off = 16; off; off >>= 1) m = fmaxf(m, __shfl_xor_sync(0xffffffffu, m, off));
    if (lane == 0) red[wid] = m;
    __syncthreads();
    if (tid < NATT) {
        int k4 = (tid >> 7) << 2;
        float rm = fmaxf(fmaxf(red[k4], red[k4 + 1]), fmaxf(red[k4 + 2], red[k4 + 3]));
        xv = expf(xv - rm);
    } else xv = 0.0f;
    __syncthreads();
    float s = xv;
#pragma unroll
    for (int off = 16; off; off >>= 1) s += __shfl_xor_sync(0xffffffffu, s, off);
    if (lane == 0) red[wid] = s;
    __syncthreads();
    if (tid < NATT) {
        int k4 = (tid >> 7) << 2;
        float rs = red[k4] + red[k4 + 1] + red[k4 + 2] + red[k4 + 3];
        alp[tid] = xv / rs;
    }
    __syncthreads();

    float acc = 0.0f;
    const int k = tid / DIN, d = tid - k * DIN;
    const f16* Xb = g_Xh + (size_t)b * (L_ * DIN);
    for (int lc = 0; lc < L_; lc += 16) {
        for (int i = tid; i < 16 * DIN; i += 416) xs[i] = __half2float(Xb[lc * DIN + i]);
        __syncthreads();
        if (tid < 390) {
#pragma unroll
            for (int l = 0; l < 16; l++) acc += alp[k * L_ + lc + l] * xs[l * DIN + d];
        }
        __syncthreads();
    }
    if (tid < 390) {
        f16 hi = __float2half_rn(acc);
        size_t off = (size_t)(tid >> 5) * (B_ * 32) + swz(b, tid & 31);
        wHi[off] = hi;
        wLo[off] = __float2half_rn(acc - __half2float(hi));
    }
}

// ---------------- fused tail ----------------
__global__ void k_tail(const float* __restrict__ Fe, const float* __restrict__ W_d1,
                       const float* __restrict__ b_d1, const float* __restrict__ W_r,
                       const float* __restrict__ b_r, const float* __restrict__ W_a,
                       const float* __restrict__ W_d2, const float* __restrict__ b_d2,
                       float* __restrict__ out) {
    __shared__ float hs[H_];
    __shared__ float yb[FEAT_];
    __shared__ float r1[PROJ_], r2[PROJ_], sb[PROJ_];
    __shared__ float aw[2];
    const int b = blockIdx.x, tid = threadIdx.x;   // 64 threads
    for (int i = tid; i < H_; i += 64) hs[i] = g_hmax[(size_t)b * H_ + i];
    __syncthreads();
    if (tid < FEAT_) {
        float a = b_d1[tid];
        const float* w = W_d1 + tid * H_;
        for (int k2 = 0; k2 < H_; k2++) a += hs[k2] * w[k2];
        yb[tid] = fmaxf(a, 0.0f);
    }
    __syncthreads();
    if (tid < PROJ_) {
        float a = b_r[tid], a2 = b_r[tid];
        const float* w = W_r + tid * FEAT_;
        const float* fe = Fe + b * FEAT_;
        for (int q = 0; q < FEAT_; q++) { a += yb[q] * w[q]; a2 += fe[q] * w[q]; }
        r1[tid] = a  > 0.0f ? a  : 0.01f * a;
        r2[tid] = a2 > 0.0f ? a2 : 0.01f * a2;
    }
    __syncthreads();
    if (tid == 0) {
        float s1 = 0.0f, s2 = 0.0f;
        for (int p = 0; p < PROJ_; p++) { s1 += tanhf(r1[p]) * W_a[p]; s2 += tanhf(r2[p]) * W_a[p]; }
        float mx = fmaxf(s1, s2);
        float e1 = expf(s1 - mx), e2 = expf(s2 - mx);
        float inv = 1.0f / (e1 + e2);
        aw[0] = e1 * inv; aw[1] = e2 * inv;
    }
    __syncthreads();
    if (tid < PROJ_) sb[tid] = fmaxf(aw[0] * r1[tid] + aw[1] * r2[tid], 0.0f);
    __syncthreads();
    if (tid < 2) {
        float a = b_d2[tid];
        const float* w = W_d2 + tid * PROJ_;
        for (int p = 0; p < PROJ_; p++) a += sb[p] * w[p];
        out[b * 2 + tid] = a;
    }
}

// ---------------- launch ----------------
extern "C" void kernel_launch(void* const* d_in, const int* in_sizes, int n_in,
                              void* d_out, int out_size) {
    const float* X     = (const float*)d_in[0];
    const float* Fe    = (const float*)d_in[1];
    const float* W_att = (const float*)d_in[2];
    const float* b_att = (const float*)d_in[3];
    const float* W_ih  = (const float*)d_in[4];
    const float* W_hh  = (const float*)d_in[5];
    const float* b_ih  = (const float*)d_in[6];
    const float* b_hh  = (const float*)d_in[7];
    const float* W_d1  = (const float*)d_in[8];
    const float* b_d1  = (const float*)d_in[9];
    const float* W_r   = (const float*)d_in[10];
    const float* b_r   = (const float*)d_in[11];
    const float* W_a   = (const float*)d_in[12];
    const float* W_d2  = (const float*)d_in[13];
    const float* b_d2  = (const float*)d_in[14];
    float* out = (float*)d_out;

    f16 *Ah0, *Al0, *Ah1, *Al1, *Whi, *Lhi;
    float *bsum;
    cudaGetSymbolAddress((void**)&Ah0, g_Ahi0);
    cudaGetSymbolAddress((void**)&Al0, g_Alo0);
    cudaGetSymbolAddress((void**)&Ah1, g_Ahi1);
    cudaGetSymbolAddress((void**)&Al1, g_Alo1);
    cudaGetSymbolAddress((void**)&Whi, g_Whi);
    cudaGetSymbolAddress((void**)&Lhi, g_Lhi);
    cudaGetSymbolAddress((void**)&bsum, g_bsum);

    // gates: 4 stages x (2*128 + 192) * 64B = 114688 B
    constexpr int DSMEM_G = NSTG * (2 * 128 + 192) * 64;
    // logits: 4 stages x (2*64 + 64) * 64B = 49152 B
    constexpr int DSMEM_L = NSTG * (2 * 64 + 64) * 64;
    cudaFuncSetAttribute((const void*)k_mma<128, 192, 32, 48, true,  NG,   37, 0>,
                         cudaFuncAttributeMaxDynamicSharedMemorySize, DSMEM_G);
    cudaFuncSetAttribute((const void*)k_mma<64, 64, 32, 16, false, NATT, 24, 13>,
                         cudaFuncAttributeMaxDynamicSharedMemorySize, DSMEM_L);

    k_init<<<2048, 256>>>(X, W_att, W_ih, W_hh, b_ih, b_hh);

    for (int t = 0; t < L_; t++) {
        f16* rdHi = (t & 1) ? Ah1 : Ah0;
        f16* rdLo = (t & 1) ? Al1 : Al0;
        f16* wrHi = (t & 1) ? Ah0 : Ah1;
        f16* wrLo = (t & 1) ? Al0 : Al1;
        // logits[1024,384] = h @ Wl + b_att   (A chunks 13..36)
        k_mma<64, 64, 32, 16, false, NATT, 24, 13><<<dim3(NATT / 64, B_ / 64), 256, DSMEM_L>>>(
            rdHi, rdLo, nullptr, nullptr, Lhi, b_att);
        // softmax + attention pooling -> v chunks 0..12 of rd buffer
        k_attn<<<B_, 416>>>(rdHi, rdLo);
        // gates = [v|h] @ Wcat + bsum, fused LSTM cell -> h; 16 warps, warp tile 32x48
        k_mma<128, 192, 32, 48, true, NG, 37, 0><<<dim3(NG / 192, B_ / 128), 512, DSMEM_G>>>(
            rdHi, rdLo, wrHi, wrLo, Whi, bsum);
    }

    k_tail<<<B_, 64>>>(Fe, W_d1, b_d1, W_r, b_r, W_a, W_d2, b_d2, out);
}

// round 16
// speedup vs baseline: 1.0025x; 1.0025x over previous
#include <cuda_runtime.h>
#include <cuda_fp16.h>
#include <math.h>
#include <float.h>
#include <stdint.h>

#define B_    1024
#define L_    128
#define DIN   130
#define H_    768
#define FEAT_ 49
#define PROJ_ 40
#define NG    3072          // 4*H
#define NATT  384           // 3*L
#define NCHK  37            // K chunks of 32: v chunks 0..12, h chunks 13..36
#define KTOT  1184
#define HOFF  416           // h starts at k=416 (chunk 13)
#define NSTG  4

typedef __half f16;

// ---------------- device scratch (chunked, swizzled layouts) ----------------
__device__ f16 g_Ahi0[NCHK*B_*32], g_Alo0[NCHK*B_*32];
__device__ f16 g_Ahi1[NCHK*B_*32], g_Alo1[NCHK*B_*32];
__device__ f16 g_Whi[NCHK*NG*32];                       // gates W^T chunked [c][n_perm][32]
__device__ f16 g_Lhi[24*NATT*32];                       // logits W^T chunked [c][n][32]
__device__ f16 g_Xh[B_*L_*DIN];                         // X in fp16
__device__ float g_bsum[NG];
__device__ float g_c[B_*H_], g_hmax[B_*H_];
__device__ float g_logits[B_*NATT];

// ---------------- helpers ----------------
__device__ __forceinline__ uint32_t smem_u32(const void* p) {
    return (uint32_t)__cvta_generic_to_shared(p);
}
__device__ __forceinline__ int swz(int row, int kk) {
    int seg = ((kk >> 3) ^ (row + (row >> 2))) & 3;
    return row * 32 + seg * 8 + (kk & 7);
}
__device__ __forceinline__ void bulk_cp(uint32_t dst, const void* src, uint32_t bytes,
                                        uint32_t mbar) {
    asm volatile("cp.async.bulk.shared::cluster.global.mbarrier::complete_tx::bytes "
                 "[%0], [%1], %2, [%3];"
                 :: "r"(dst), "l"(__cvta_generic_to_global(src)), "r"(bytes), "r"(mbar)
                 : "memory");
}
__device__ __forceinline__ void mbar_init(uint32_t a, uint32_t cnt) {
    asm volatile("mbarrier.init.shared.b64 [%0], %1;" :: "r"(a), "r"(cnt) : "memory");
}
__device__ __forceinline__ void mbar_expect(uint32_t a, uint32_t tx) {
    asm volatile("mbarrier.arrive.expect_tx.shared.b64 _, [%0], %1;"
                 :: "r"(a), "r"(tx) : "memory");
}
__device__ __forceinline__ void mbar_wait(uint32_t a, uint32_t ph) {
    asm volatile(
        "{\n\t.reg .pred P;\n"
        "WL%=:\n\t"
        "mbarrier.try_wait.parity.acquire.cta.shared::cta.b64 P, [%0], %1, 0x989680;\n\t"
        "@P bra WD%=;\n\t"
        "bra WL%=;\n"
        "WD%=:\n\t}"
        :: "r"(a), "r"(ph) : "memory");
}

#define LDSM4(r, a) \
    asm volatile("ldmatrix.sync.aligned.m8n8.x4.shared.b16 {%0,%1,%2,%3}, [%4];" \
        : "=r"((r)[0]), "=r"((r)[1]), "=r"((r)[2]), "=r"((r)[3]) : "r"(a))

__device__ __forceinline__ void mma16816(float* d, const uint32_t* a, const uint32_t* b) {
    asm volatile("mma.sync.aligned.m16n8k16.row.col.f32.f16.f16.f32 "
        "{%0,%1,%2,%3}, {%4,%5,%6,%7}, {%8,%9}, {%0,%1,%2,%3};"
        : "+f"(d[0]), "+f"(d[1]), "+f"(d[2]), "+f"(d[3])
        : "r"(a[0]), "r"(a[1]), "r"(a[2]), "r"(a[3]), "r"(b[0]), "r"(b[1]));
}

__device__ __forceinline__ float sigmf(float x) { return 1.0f / (1.0f + __expf(-x)); }

// ---------------- init ----------------
// permuted col n = 16q + 8h + 2a + e  <->  gate (2h+e) of hidden j = 4q + a
__global__ void k_init(const float* __restrict__ X,
                       const float* __restrict__ W_att, const float* __restrict__ W_ih,
                       const float* __restrict__ W_hh, const float* __restrict__ b_ih,
                       const float* __restrict__ b_hh) {
    long g = (long)blockIdx.x * blockDim.x + threadIdx.x;
    long stride = (long)gridDim.x * blockDim.x;
    for (long i = g; i < (long)NG * KTOT; i += stride) {
        int n = (int)(i / KTOT), k = (int)(i % KTOT);
        int q = n >> 4, r = n & 15;
        int gate = ((r >> 3) << 1) | (r & 1);
        int j = (q << 2) + ((r & 7) >> 1);
        int srow = gate * H_ + j;
        float w = 0.0f;
        if (k < 390)                         w = W_ih[(size_t)srow * 390 + k];
        else if (k >= HOFF && k < HOFF + H_) w = W_hh[(size_t)srow * H_ + (k - HOFF)];
        g_Whi[(size_t)(k >> 5) * (NG * 32) + swz(n, k & 31)] = __float2half_rn(w);
    }
    for (long i = g; i < (long)NATT * H_; i += stride) {
        int n = (int)(i / H_), k = (int)(i % H_);
        int ks = n >> 7, l = n & 127;
        float w = W_att[(size_t)ks * (H_ * L_) + (size_t)k * L_ + l];
        g_Lhi[(size_t)(k >> 5) * (NATT * 32) + swz(n, k & 31)] = __float2half_rn(w);
    }
    for (long i = g; i < (long)B_ * L_ * DIN; i += stride)
        g_Xh[i] = __float2half_rn(X[i]);
    for (long i = g; i < NG; i += stride) {
        int n = (int)i;
        int q = n >> 4, r = n & 15;
        int gate = ((r >> 3) << 1) | (r & 1);
        int j = (q << 2) + ((r & 7) >> 1);
        g_bsum[i] = b_ih[gate * H_ + j] + b_hh[gate * H_ + j];
    }
    f16 z = __float2half_rn(0.0f);
    for (long i = g; i < (long)NCHK * B_ * 32; i += stride) {
        g_Ahi0[i] = z; g_Alo0[i] = z; g_Ahi1[i] = z; g_Alo1[i] = z;
    }
    for (long i = g; i < (long)B_ * H_; i += stride) { g_c[i] = 0.0f; g_hmax[i] = -FLT_MAX; }
}

// ---------------- bulk-fed mma.sync GEMM, fp16 A-hi/lo x B (2 products) ----------------
// Warp tile WM x WN. NSTG-stage mbarrier ring fed by cp.async.bulk.
template <int BM, int BN, int WM, int WN, bool GATES, int BROWS, int NCH, int CA0>
__global__ void __launch_bounds__((BM / WM) * (BN / WN) * 32, 1)
k_mma(const f16* __restrict__ gAhi, const f16* __restrict__ gAlo,
      f16* __restrict__ wAhi, f16* __restrict__ wAlo,
      const f16* __restrict__ gBhi, const float* __restrict__ bias) {
    constexpr int NWX = BN / WN, NWY = BM / WM;
    constexpr int MT = WM / 16;
    constexpr int NTHR = NWX * NWY * 32;
    constexpr int NB16 = WN / 16;
    constexpr uint32_t A_BYTES = (uint32_t)BM * 64u;
    constexpr uint32_t B_BYTES = (uint32_t)BN * 64u;
    constexpr uint32_t STAGE_B = 2u * A_BYTES + B_BYTES;
    constexpr uint32_t TXB = STAGE_B;

    extern __shared__ __align__(128) char dyn[];
    __shared__ __align__(8) uint64_t s_mbar[NSTG];
    __shared__ float s_bias[BN];

    const int tid = threadIdx.x, w = tid >> 5, lane = tid & 31;
    const int wx = w % NWX, wy = w / NWX;
    const int m0 = blockIdx.y * BM, n0 = blockIdx.x * BN;
    const uint32_t smb = smem_u32(dyn);
    const uint32_t mb0 = smem_u32(&s_mbar[0]);

    if (tid == 0) {
#pragma unroll
        for (int i = 0; i < NSTG; i++) mbar_init(mb0 + 8u * i, 1);
    }
    for (int i = tid; i < BN; i += NTHR) s_bias[i] = bias[n0 + i];
    __syncthreads();

    auto issue = [&](int k) {
        uint32_t buf = smb + (uint32_t)(k % NSTG) * STAGE_B;
        uint32_t mb = mb0 + 8u * (k % NSTG);
        mbar_expect(mb, TXB);
        const char* srcAh = (const char*)gAhi + ((size_t)(CA0 + k) * B_ + m0) * 64;
        const char* srcAl = (const char*)gAlo + ((size_t)(CA0 + k) * B_ + m0) * 64;
        const char* srcBh = (const char*)gBhi + ((size_t)k * BROWS + n0) * 64;
        bulk_cp(buf,               srcAh, A_BYTES, mb);
        bulk_cp(buf + A_BYTES,     srcAl, A_BYTES, mb);
        bulk_cp(buf + 2 * A_BYTES, srcBh, B_BYTES, mb);
    };
    if (tid == 0) { issue(0); issue(1); issue(2); }

    float acc[MT][WN / 8][4];
#pragma unroll
    for (int i = 0; i < MT; i++)
#pragma unroll
        for (int j = 0; j < WN / 8; j++)
#pragma unroll
            for (int k = 0; k < 4; k++) acc[i][j][k] = 0.0f;

    for (int s = 0; s < NCH; s++) {
        if (tid == 0 && s + 3 < NCH) issue(s + 3);
        mbar_wait(mb0 + 8u * (s % NSTG), (uint32_t)((s / NSTG) & 1));

        const uint32_t st  = smb + (uint32_t)(s % NSTG) * STAGE_B;
        const uint32_t stB = st + 2 * A_BYTES;
#pragma unroll
        for (int ks = 0; ks < 2; ks++) {
            uint32_t ah[MT][4], al[MT][4];
#pragma unroll
            for (int mt = 0; mt < MT; mt++) {
                int row = wy * WM + mt * 16 + (lane & 15);
                int seg = (ks * 2 + (lane >> 4)) ^ ((row + (row >> 2)) & 3);
                uint32_t addr = st + (uint32_t)(row * 64 + (seg & 3) * 16);
                LDSM4(ah[mt], addr);
                LDSM4(al[mt], addr + A_BYTES);
            }
#pragma unroll
            for (int nb = 0; nb < NB16; nb++) {
                uint32_t bh[4];
                {
                    int gg = lane >> 3;
                    int row = wx * WN + nb * 16 + ((gg >> 1) << 3) + (lane & 7);
                    int seg = (ks * 2 + (gg & 1)) ^ ((row + (row >> 2)) & 3);
                    uint32_t addr = stB + (uint32_t)(row * 64 + (seg & 3) * 16);
                    LDSM4(bh, addr);
                }
#pragma unroll
                for (int mt = 0; mt < MT; mt++)
#pragma unroll
                    for (int j2 = 0; j2 < 2; j2++) {
                        float* a = acc[mt][nb * 2 + j2];
                        mma16816(a, ah[mt], &bh[j2 * 2]);
                        mma16816(a, al[mt], &bh[j2 * 2]);
                    }
            }
        }
        __syncthreads();
    }

    const int a_ = lane & 3, rl = lane >> 2;
    if constexpr (GATES) {
        // stage h (hi/lo) in smem, then coalesced uint4 writes
        constexpr int JW = BN / 4;                    // 48 j per CTA
        f16* sh_hi = (f16*)dyn;                       // [BM][JW]
        f16* sh_lo = (f16*)dyn + BM * JW;
        const int j0 = n0 >> 2;
#pragma unroll
        for (int mt = 0; mt < MT; mt++)
#pragma unroll
            for (int p = 0; p < WN / 16; p++) {
                const int colb = wx * WN + p * 16;
                const float bi = s_bias[colb + 2 * a_];
                const float bf = s_bias[colb + 2 * a_ + 1];
                const float bg = s_bias[colb + 8 + 2 * a_];
                const float bo = s_bias[colb + 8 + 2 * a_ + 1];
                const int jl = (colb >> 2) + a_;
                const int j = j0 + jl;
#pragma unroll
                for (int rh = 0; rh < 2; rh++) {
                    float iv = acc[mt][2 * p][2 * rh]     + bi;
                    float fv = acc[mt][2 * p][2 * rh + 1] + bf;
                    float gv = acc[mt][2 * p + 1][2 * rh]     + bg;
                    float ov = acc[mt][2 * p + 1][2 * rh + 1] + bo;
                    int row = wy * WM + mt * 16 + rh * 8 + rl;
                    int b = m0 + row;
                    size_t cidx = (size_t)b * H_ + j;
                    float c = sigmf(fv) * g_c[cidx] + sigmf(iv) * tanhf(gv);
                    float h = sigmf(ov) * tanhf(c);
                    g_c[cidx] = c;
                    g_hmax[cidx] = fmaxf(g_hmax[cidx], h);
                    f16 hh = __float2half_rn(h);
                    sh_hi[row * JW + jl] = hh;
                    sh_lo[row * JW + jl] = __float2half_rn(h - __half2float(hh));
                }
            }
        __syncthreads();
        for (int i = tid; i < BM * (JW / 8); i += NTHR) {
            int row = i / (JW / 8), s8 = i % (JW / 8);
            int j = j0 + s8 * 8;
            int chunk = 13 + (j >> 5);
            int kk = j & 31;
            int b = m0 + row;
            int seg = ((kk >> 3) ^ (b + (b >> 2))) & 3;
            size_t dst = (size_t)chunk * (B_ * 32) + (size_t)b * 32 + seg * 8;
            *(uint4*)(wAhi + dst) = *(const uint4*)(sh_hi + row * JW + s8 * 8);
            *(uint4*)(wAlo + dst) = *(const uint4*)(sh_lo + row * JW + s8 * 8);
        }
    } else {
#pragma unroll
        for (int mt = 0; mt < MT; mt++)
#pragma unroll
            for (int nt = 0; nt < WN / 8; nt++) {
                const int lc = wx * WN + nt * 8 + 2 * a_;
#pragma unroll
                for (int rh = 0; rh < 2; rh++) {
                    int row = m0 + wy * WM + mt * 16 + rh * 8 + rl;
                    float2 v;
                    v.x = acc[mt][nt][2 * rh]     + s_bias[lc];
                    v.y = acc[mt][nt][2 * rh + 1] + s_bias[lc + 1];
                    *(float2*)&g_logits[(size_t)row * NATT + n0 + lc] = v;
                }
            }
    }
}

// ---------------- fused softmax + attention pooling (fp16 X, writes v hi/lo) ----------
__global__ void k_attn(f16* __restrict__ wHi, f16* __restrict__ wLo) {
    __shared__ float alp[NATT];
    __shared__ float xs[16 * DIN];
    __shared__ float red[16];
    const int b = blockIdx.x;
    const int tid = threadIdx.x;
    for (int i = tid; i < NATT; i += 416) alp[i] = g_logits[b * NATT + i];
    __syncthreads();

    const int wid = tid >> 5, lane = tid & 31;
    float xv = (tid < NATT) ? alp[tid] : -FLT_MAX;
    float m = xv;
#pragma unroll
    for (int off = 16; off; off >>= 1) m = fmaxf(m, __shfl_xor_sync(0xffffffffu, m, off));
    if (lane == 0) red[wid] = m;
    __syncthreads();
    if (tid < NATT) {
        int k4 = (tid >> 7) << 2;
        float rm = fmaxf(fmaxf(red[k4], red[k4 + 1]), fmaxf(red[k4 + 2], red[k4 + 3]));
        xv = expf(xv - rm);
    } else xv = 0.0f;
    __syncthreads();
    float s = xv;
#pragma unroll
    for (int off = 16; off; off >>= 1) s += __shfl_xor_sync(0xffffffffu, s, off);
    if (lane == 0) red[wid] = s;
    __syncthreads();
    if (tid < NATT) {
        int k4 = (tid >> 7) << 2;
        float rs = red[k4] + red[k4 + 1] + red[k4 + 2] + red[k4 + 3];
        alp[tid] = xv / rs;
    }
    __syncthreads();

    float acc = 0.0f;
    const int k = tid / DIN, d = tid - k * DIN;
    const f16* Xb = g_Xh + (size_t)b * (L_ * DIN);
    for (int lc = 0; lc < L_; lc += 16) {
        for (int i = tid; i < 16 * DIN; i += 416) xs[i] = __half2float(Xb[lc * DIN + i]);
        __syncthreads();
        if (tid < 390) {
#pragma unroll
            for (int l = 0; l < 16; l++) acc += alp[k * L_ + lc + l] * xs[l * DIN + d];
        }
        __syncthreads();
    }
    if (tid < 390) {
        f16 hi = __float2half_rn(acc);
        size_t off = (size_t)(tid >> 5) * (B_ * 32) + swz(b, tid & 31);
        wHi[off] = hi;
        wLo[off] = __float2half_rn(acc - __half2float(hi));
    }
}

// ---------------- fused tail ----------------
__global__ void k_tail(const float* __restrict__ Fe, const float* __restrict__ W_d1,
                       const float* __restrict__ b_d1, const float* __restrict__ W_r,
                       const float* __restrict__ b_r, const float* __restrict__ W_a,
                       const float* __restrict__ W_d2, const float* __restrict__ b_d2,
                       float* __restrict__ out) {
    __shared__ float hs[H_];
    __shared__ float yb[FEAT_];
    __shared__ float r1[PROJ_], r2[PROJ_], sb[PROJ_];
    __shared__ float aw[2];
    const int b = blockIdx.x, tid = threadIdx.x;   // 64 threads
    for (int i = tid; i < H_; i += 64) hs[i] = g_hmax[(size_t)b * H_ + i];
    __syncthreads();
    if (tid < FEAT_) {
        float a = b_d1[tid];
        const float* w = W_d1 + tid * H_;
        for (int k2 = 0; k2 < H_; k2++) a += hs[k2] * w[k2];
        yb[tid] = fmaxf(a, 0.0f);
    }
    __syncthreads();
    if (tid < PROJ_) {
        float a = b_r[tid], a2 = b_r[tid];
        const float* w = W_r + tid * FEAT_;
        const float* fe = Fe + b * FEAT_;
        for (int q = 0; q < FEAT_; q++) { a += yb[q] * w[q]; a2 += fe[q] * w[q]; }
        r1[tid] = a  > 0.0f ? a  : 0.01f * a;
        r2[tid] = a2 > 0.0f ? a2 : 0.01f * a2;
    }
    __syncthreads();
    if (tid == 0) {
        float s1 = 0.0f, s2 = 0.0f;
        for (int p = 0; p < PROJ_; p++) { s1 += tanhf(r1[p]) * W_a[p]; s2 += tanhf(r2[p]) * W_a[p]; }
        float mx = fmaxf(s1, s2);
        float e1 = expf(s1 - mx), e2 = expf(s2 - mx);
        float inv = 1.0f / (e1 + e2);
        aw[0] = e1 * inv; aw[1] = e2 * inv;
    }
    __syncthreads();
    if (tid < PROJ_) sb[tid] = fmaxf(aw[0] * r1[tid] + aw[1] * r2[tid], 0.0f);
    __syncthreads();
    if (tid < 2) {
        float a = b_d2[tid];
        const float* w = W_d2 + tid * PROJ_;
        for (int p = 0; p < PROJ_; p++) a += sb[p] * w[p];
        out[b * 2 + tid] = a;
    }
}

// ---------------- launch ----------------
extern "C" void kernel_launch(void* const* d_in, const int* in_sizes, int n_in,
                              void* d_out, int out_size) {
    const float* X     = (const float*)d_in[0];
    const float* Fe    = (const float*)d_in[1];
    const float* W_att = (const float*)d_in[2];
    const float* b_att = (const float*)d_in[3];
    const float* W_ih  = (const float*)d_in[4];
    const float* W_hh  = (const float*)d_in[5];
    const float* b_ih  = (const float*)d_in[6];
    const float* b_hh  = (const float*)d_in[7];
    const float* W_d1  = (const float*)d_in[8];
    const float* b_d1  = (const float*)d_in[9];
    const float* W_r   = (const float*)d_in[10];
    const float* b_r   = (const float*)d_in[11];
    const float* W_a   = (const float*)d_in[12];
    const float* W_d2  = (const float*)d_in[13];
    const float* b_d2  = (const float*)d_in[14];
    float* out = (float*)d_out;

    f16 *Ah0, *Al0, *Ah1, *Al1, *Whi, *Lhi;
    float *bsum;
    cudaGetSymbolAddress((void**)&Ah0, g_Ahi0);
    cudaGetSymbolAddress((void**)&Al0, g_Alo0);
    cudaGetSymbolAddress((void**)&Ah1, g_Ahi1);
    cudaGetSymbolAddress((void**)&Al1, g_Alo1);
    cudaGetSymbolAddress((void**)&Whi, g_Whi);
    cudaGetSymbolAddress((void**)&Lhi, g_Lhi);
    cudaGetSymbolAddress((void**)&bsum, g_bsum);

    // gates: 4 stages x (2*128 + 192) * 64B = 114688 B
    constexpr int DSMEM_G = NSTG * (2 * 128 + 192) * 64;
    // logits: 4 stages x (2*64 + 64) * 64B = 49152 B
    constexpr int DSMEM_L = NSTG * (2 * 64 + 64) * 64;
    cudaFuncSetAttribute((const void*)k_mma<128, 192, 32, 48, true,  NG,   37, 0>,
                         cudaFuncAttributeMaxDynamicSharedMemorySize, DSMEM_G);
    cudaFuncSetAttribute((const void*)k_mma<64, 64, 32, 16, false, NATT, 24, 13>,
                         cudaFuncAttributeMaxDynamicSharedMemorySize, DSMEM_L);

    k_init<<<2048, 256>>>(X, W_att, W_ih, W_hh, b_ih, b_hh);

    for (int t = 0; t < L_; t++) {
        f16* rdHi = (t & 1) ? Ah1 : Ah0;
        f16* rdLo = (t & 1) ? Al1 : Al0;
        f16* wrHi = (t & 1) ? Ah0 : Ah1;
        f16* wrLo = (t & 1) ? Al0 : Al1;
        // logits[1024,384] = h @ Wl + b_att   (A chunks 13..36)
        k_mma<64, 64, 32, 16, false, NATT, 24, 13><<<dim3(NATT / 64, B_ / 64), 256, DSMEM_L>>>(
            rdHi, rdLo, nullptr, nullptr, Lhi, b_att);
        // softmax + attention pooling -> v chunks 0..12 of rd buffer
        k_attn<<<B_, 416>>>(rdHi, rdLo);
        // gates = [v|h] @ Wcat + bsum, fused LSTM cell -> h; 16 warps, warp tile 32x48
        k_mma<128, 192, 32, 48, true, NG, 37, 0><<<dim3(NG / 192, B_ / 128), 512, DSMEM_G>>>(
            rdHi, rdLo, wrHi, wrLo, Whi, bsum);
    }

    k_tail<<<B_, 64>>>(Fe, W_d1, b_d1, W_r, b_r, W_a, W_d2, b_d2, out);
}